// round 16
// baseline (speedup 1.0000x reference)
#include <cuda_runtime.h>
#include <cuda_bf16.h>
#include <cstdint>

#define SEQ  2048
#define DIM  64
#define NBLK 256          // 16 batches x 16 s-chunks of 128 rows; 2 CTAs/SM
#define NT   256

// Double-buffered reduced M per batch, P layout [d2][d1]: 2 x 16 x 4096 fp32.
// Buffer parity = grid-barrier generation & 1 (one barrier per launch).
// Zero-initialized at module load; each launch zeroes the OTHER buffer for
// the next launch (stream-ordered => race-free).
__device__ float M_final[2][16 * DIM * DIM];
__device__ unsigned bar_cnt = 0;
__device__ volatile unsigned bar_gen = 0;

// smem tile byte offsets (36KB/CTA). Row stride 144B = 64 bf16 + 16B pad
// (16B-multiple for ldmatrix; 36-word stride -> conflict-free bank walk).
#define T_HI0   0        // Khi   | MThi
#define T_LO0   9216     // Klo   | MTlo
#define T_HI1   18432    // Qhi   | Vhi
#define T_LO1   27648    // Qlo   | Vlo
#define TROW    144

__device__ __forceinline__ uint32_t smem_u32(const void* p){
    uint32_t a;
    asm("{ .reg .u64 t; cvta.to.shared.u64 t, %1; cvt.u32.u64 %0, t; }" : "=r"(a) : "l"(p));
    return a;
}
__device__ __forceinline__ uint32_t bf16x2_of(float fo, float fe){
    uint32_t r;
    asm("cvt.rn.bf16x2.f32 %0, %1, %2;" : "=r"(r) : "f"(fo), "f"(fe));
    return r;
}
// split fp32 (fe=even idx, fo=odd idx) -> hi word {bf16(fo),bf16(fe)} + residual word
__device__ __forceinline__ void cvt_pair(float fe, float fo, uint32_t &hi, uint32_t &lo){
    hi = bf16x2_of(fo, fe);
    float he = __uint_as_float(hi << 16);
    float ho = __uint_as_float(hi & 0xffff0000u);
    lo = bf16x2_of(fo - ho, fe - he);
}
__device__ __forceinline__ void mma16816(float* c, const uint32_t* a,
                                         uint32_t b0, uint32_t b1){
    asm("mma.sync.aligned.m16n8k16.row.col.f32.bf16.bf16.f32 "
        "{%0,%1,%2,%3}, {%4,%5,%6,%7}, {%8,%9}, {%0,%1,%2,%3};"
        : "+f"(c[0]), "+f"(c[1]), "+f"(c[2]), "+f"(c[3])
        : "r"(a[0]), "r"(a[1]), "r"(a[2]), "r"(a[3]), "r"(b0), "r"(b1));
}
__device__ __forceinline__ void ldsm4(uint32_t* r, uint32_t addr){
    asm volatile("ldmatrix.sync.aligned.m8n8.x4.shared.b16 {%0,%1,%2,%3}, [%4];"
        : "=r"(r[0]), "=r"(r[1]), "=r"(r[2]), "=r"(r[3]) : "r"(addr));
}
__device__ __forceinline__ void ldsm4t(uint32_t* r, uint32_t addr){
    asm volatile("ldmatrix.sync.aligned.m8n8.x4.trans.shared.b16 {%0,%1,%2,%3}, [%4];"
        : "=r"(r[0]), "=r"(r[1]), "=r"(r[2]), "=r"(r[3]) : "r"(addr));
}
__device__ __forceinline__ void grid_barrier(){
    __threadfence();
    __syncthreads();
    if (threadIdx.x == 0) {
        unsigned gen = bar_gen;
        unsigned arrived = atomicAdd(&bar_cnt, 1);
        if (arrived == gridDim.x - 1) {
            bar_cnt = 0;
            __threadfence();
            bar_gen = gen + 1;
        } else {
            while (bar_gen == gen) { __nanosleep(64); }   // backoff: no L2 poll storm
        }
    }
    __syncthreads();
    __threadfence();
}

// Stage 16 fp32 (one row-chunk) as bf16 hi+lo into natural-layout tiles.
__device__ __forceinline__ void stage_tile(unsigned char* hiB, unsigned char* loB,
                                           const float4* f, int row, int chunk){
    uint32_t h[8], L[8];
#pragma unroll
    for (int j = 0; j < 4; j++){
        cvt_pair(f[j].x, f[j].y, h[2*j],   L[2*j]);
        cvt_pair(f[j].z, f[j].w, h[2*j+1], L[2*j+1]);
    }
    uint4* dh = (uint4*)(hiB + row * TROW + chunk * 32);
    dh[0] = make_uint4(h[0], h[1], h[2], h[3]);
    dh[1] = make_uint4(h[4], h[5], h[6], h[7]);
    uint4* dl = (uint4*)(loB + row * TROW + chunk * 32);
    dl[0] = make_uint4(L[0], L[1], L[2], L[3]);
    dl[1] = make_uint4(L[4], L[5], L[6], L[7]);
}

// ---------------------------------------------------------------------------
// 256 blocks x 256 threads, 2 CTAs/SM. ONE grid barrier.
// Phase A (pipelined): LDG sub0 -> stage -> sync -> [LDG sub1 || MMA sub0]
//   -> sync -> stage sub1 -> sync -> MMA sub1 -> [LDG V vt0 || atomic epi]
//   -> zero other M buffer -> sync -> stage V vt0.
// barrier -> Phase C: [LDG MT + LDG V vt1] -> stage MT -> sync -> MMA vt0
//   -> sync -> stage vt1 -> sync -> MMA vt1.
// ---------------------------------------------------------------------------
__global__ __launch_bounds__(NT, 2)
void fused_attn_hmma6(const float* __restrict__ Q, const float* __restrict__ K,
                      const float* __restrict__ V, float* __restrict__ O)
{
    __shared__ __align__(16) unsigned char sm[36864];
    const uint32_t sb = smem_u32(sm);

    const int t = threadIdx.x, warp = t >> 5, lane = t & 31;
    const int g = lane >> 2, tg = lane & 3;         // mma C/epilogue ids
    const int grp = lane >> 3, li = lane & 7;       // ldmatrix ids
    const int half8 = (grp & 1) << 3;
    const int krow  = ((grp >> 1) << 3) + li;       // trans-ldmatrix stored row
    const int wm = warp & 3, wn = warp >> 2;        // warp tile m0=16wm, n0=32wn
    const int m0 = wm * 16, n0 = wn * 32;
    const int blk = blockIdx.x, b = blk >> 4, c = blk & 15;

    // Buffer parity: consistent across all blocks (bar_gen only increments
    // at the single barrier, which every block reaches after reading this).
    const int p = (int)(bar_gen & 1u);

    const float* Kc = K + ((size_t)b * SEQ + (size_t)c * 128) * DIM;
    const float* Qc = Q + ((size_t)b * SEQ + (size_t)c * 128) * DIM;
    const float* Vc = V + ((size_t)b * SEQ + (size_t)c * 128) * DIM;

    const int srow = t >> 2, schunk = t & 3;        // staging coords (64 rows x 4 chunks)

    // ========================== Phase A (pipelined) ========================
    float4 fV[4];                                    // V vt0 prefetch regs
    {
        float acc[4][4];
#pragma unroll
        for (int q = 0; q < 4; q++)
#pragma unroll
            for (int i = 0; i < 4; i++) acc[q][i] = 0.0f;

        // trans-ldmatrix bases (K^T rows m, Q^T rows n; tiles stored [s][d])
        const uint32_t aB  = sb + T_HI0 + krow * TROW + 2 * (m0 + half8);
        const uint32_t bB0 = sb + T_HI1 + krow * TROW + 2 * (n0 + half8);
        const uint32_t bB1 = bB0 + 32;      // +16 cols

#define MMA_A() do {                                                        \
    _Pragma("unroll")                                                       \
    for (int ks = 0; ks < 4; ks++) {                                        \
        uint32_t ah[4], al[4], bh[4], bl[4];                                \
        ldsm4t(ah, aB + ks * 2304);                                         \
        ldsm4t(al, aB + ks * 2304 + 9216);                                  \
        ldsm4t(bh, bB0 + ks * 2304);                                        \
        ldsm4t(bl, bB0 + ks * 2304 + 9216);                                 \
        mma16816(acc[0], ah, bh[0], bh[2]);                                 \
        mma16816(acc[0], ah, bl[0], bl[2]);                                 \
        mma16816(acc[0], al, bh[0], bh[2]);                                 \
        mma16816(acc[1], ah, bh[1], bh[3]);                                 \
        mma16816(acc[1], ah, bl[1], bl[3]);                                 \
        mma16816(acc[1], al, bh[1], bh[3]);                                 \
        ldsm4t(bh, bB1 + ks * 2304);                                        \
        ldsm4t(bl, bB1 + ks * 2304 + 9216);                                 \
        mma16816(acc[2], ah, bh[0], bh[2]);                                 \
        mma16816(acc[2], ah, bl[0], bl[2]);                                 \
        mma16816(acc[2], al, bh[0], bh[2]);                                 \
        mma16816(acc[3], ah, bh[1], bh[3]);                                 \
        mma16816(acc[3], ah, bl[1], bl[3]);                                 \
        mma16816(acc[3], al, bh[1], bh[3]);                                 \
    }                                                                       \
} while (0)

        float4 fK[4], fQ[4];
        {   // LDG sub0
            const float4* pk = (const float4*)(Kc + (size_t)srow * DIM + schunk * 16);
            const float4* pq = (const float4*)(Qc + (size_t)srow * DIM + schunk * 16);
#pragma unroll
            for (int j = 0; j < 4; j++){ fK[j] = pk[j]; fQ[j] = pq[j]; }
        }
        stage_tile(sm + T_HI0, sm + T_LO0, fK, srow, schunk);
        stage_tile(sm + T_HI1, sm + T_LO1, fQ, srow, schunk);
        __syncthreads();

        {   // LDG sub1 — flies during MMA sub0
            const float4* pk = (const float4*)(Kc + (size_t)(64 + srow) * DIM + schunk * 16);
            const float4* pq = (const float4*)(Qc + (size_t)(64 + srow) * DIM + schunk * 16);
#pragma unroll
            for (int j = 0; j < 4; j++){ fK[j] = pk[j]; fQ[j] = pq[j]; }
        }
        MMA_A();                        // sub0
        __syncthreads();                // sub0 tile readers done
        stage_tile(sm + T_HI0, sm + T_LO0, fK, srow, schunk);
        stage_tile(sm + T_HI1, sm + T_LO1, fQ, srow, schunk);
        __syncthreads();
        MMA_A();                        // sub1
#undef MMA_A

        // LDG V vt0 — flies during the atomic epilogue
        {
            const float4* pv = (const float4*)(Vc + (size_t)srow * DIM + schunk * 16);
#pragma unroll
            for (int j = 0; j < 4; j++) fV[j] = pv[j];
        }

        // Epilogue: C[m=d1][n=d2] -> atomicAdd into M_final[p] at P[d2][d1].
        float* Mf = M_final[p] + (size_t)b * 4096;
#pragma unroll
        for (int q = 0; q < 4; q++) {
            int d2 = n0 + q * 8 + tg * 2;
            int d1 = m0 + g;
            atomicAdd(&Mf[d2 * 64 + d1],           acc[q][0]);
            atomicAdd(&Mf[(d2 + 1) * 64 + d1],     acc[q][1]);
            atomicAdd(&Mf[d2 * 64 + d1 + 8],       acc[q][2]);
            atomicAdd(&Mf[(d2 + 1) * 64 + d1 + 8], acc[q][3]);
        }
    }

    // Zero the OTHER buffer for the next launch (nobody reads it this launch;
    // cross-launch ordering is guaranteed by stream order).
    M_final[1 - p][blk * 256 + t] = 0.0f;

    __syncthreads();                    // all sub1 tile readers done
    stage_tile(sm + T_HI1, sm + T_LO1, fV, srow, schunk);   // V vt0 in place

    grid_barrier();     // all atomics into M_final[p] complete & visible

    // ========================== Phase C ====================================
    {
        // Front-batch loads: MT row-chunk (16 floats) + V vt1 (16 floats).
        float4 fM[4], fV1[4];
        {
            const int d = t >> 2, wq = t & 3;
            const float4* baseM = (const float4*)(M_final[p] + (size_t)b * 4096 + d * 64 + wq * 16);
            const float4* pv    = (const float4*)(Vc + (size_t)(64 + srow) * DIM + schunk * 16);
#pragma unroll
            for (int j = 0; j < 4; j++){ fM[j] = baseM[j]; fV1[j] = pv[j]; }
        }
        // Stage MT[d][dp] (P layout [d2=d][d1=dp]), split hi/lo.
        {
            const int d = t >> 2, wq = t & 3;
#pragma unroll
            for (int j = 0; j < 4; j++) {
                uint32_t hi, lo;
                cvt_pair(fM[j].x, fM[j].y, hi, lo);
                int w = wq * 8 + 2 * j;
                *(uint32_t*)(sm + T_HI0 + d * TROW + w * 4) = hi;
                *(uint32_t*)(sm + T_LO0 + d * TROW + w * 4) = lo;
                cvt_pair(fM[j].z, fM[j].w, hi, lo);
                *(uint32_t*)(sm + T_HI0 + d * TROW + (w + 1) * 4) = hi;
                *(uint32_t*)(sm + T_LO0 + d * TROW + (w + 1) * 4) = lo;
            }
        }
        __syncthreads();

        // non-trans ldmatrix bases: A = V rows m, B = MT rows n; k along rows
        const uint32_t vB  = sb + T_HI1 + (m0 + half8 + li) * TROW + ((grp >> 1) << 4);
        const uint32_t mB0 = sb + T_HI0 + (n0 + half8 + li) * TROW + ((grp >> 1) << 4);
        const uint32_t mB1 = mB0 + 16 * TROW;

        for (int vt = 0; vt < 2; vt++) {
            float acc2[4][4];
#pragma unroll
            for (int q = 0; q < 4; q++)
#pragma unroll
                for (int i = 0; i < 4; i++) acc2[q][i] = 0.0f;

#pragma unroll
            for (int ks = 0; ks < 4; ks++) {
                uint32_t ah[4], al[4], bh[4], bl[4];
                ldsm4(ah, vB + ks * 32);
                ldsm4(al, vB + ks * 32 + 9216);
                ldsm4(bh, mB0 + ks * 32);
                ldsm4(bl, mB0 + ks * 32 + 9216);
                mma16816(acc2[0], ah, bh[0], bh[2]);
                mma16816(acc2[0], ah, bl[0], bl[2]);
                mma16816(acc2[0], al, bh[0], bh[2]);
                mma16816(acc2[1], ah, bh[1], bh[3]);
                mma16816(acc2[1], ah, bl[1], bl[3]);
                mma16816(acc2[1], al, bh[1], bh[3]);
                ldsm4(bh, mB1 + ks * 32);
                ldsm4(bl, mB1 + ks * 32 + 9216);
                mma16816(acc2[2], ah, bh[0], bh[2]);
                mma16816(acc2[2], ah, bl[0], bl[2]);
                mma16816(acc2[2], al, bh[0], bh[2]);
                mma16816(acc2[3], ah, bh[1], bh[3]);
                mma16816(acc2[3], ah, bl[1], bl[3]);
                mma16816(acc2[3], al, bh[1], bh[3]);
            }

            // Write O rows c*128 + vt*64 + m0 + g (+8), cols n0 + q*8 + 2tg
            float* Ob = O + ((size_t)b * SEQ + (size_t)c * 128 + vt * 64 + m0) * DIM;
#pragma unroll
            for (int q = 0; q < 4; q++) {
                int col = n0 + q * 8 + tg * 2;
                *(float2*)(Ob + (size_t)g * DIM + col) =
                    make_float2(acc2[q][0], acc2[q][1]);
                *(float2*)(Ob + (size_t)(g + 8) * DIM + col) =
                    make_float2(acc2[q][2], acc2[q][3]);
            }

            if (vt == 0) {
                __syncthreads();             // frag reads of vt0 done
                stage_tile(sm + T_HI1, sm + T_LO1, fV1, srow, schunk);
                __syncthreads();
            }
        }
    }
}

// ---------------------------------------------------------------------------
extern "C" void kernel_launch(void* const* d_in, const int* in_sizes, int n_in,
                              void* d_out, int out_size) {
    const float* Q = (const float*)d_in[0];
    const float* K = (const float*)d_in[1];
    const float* V = (const float*)d_in[2];
    float* O = (float*)d_out;

    fused_attn_hmma6<<<NBLK, NT>>>(Q, K, V, O);
}

// round 17
// speedup vs baseline: 1.2193x; 1.2193x over previous
#include <cuda_runtime.h>
#include <cuda_bf16.h>
#include <cstdint>

#define SEQ  2048
#define DIM  64
#define NBLK 256          // 16 batches x 16 s-chunks of 128 rows; 2 CTAs/SM
#define NT   256

// Double-buffered reduced M per batch, P layout [d2][d1]: 2 x 16 x 4096 fp32.
// Parity = grid-barrier generation & 1 (one barrier per launch). Zero-init at
// module load; each launch zeroes the OTHER buffer for the next launch.
__device__ float M_final[2][16 * DIM * DIM];
__device__ unsigned bar_cnt = 0;
__device__ volatile unsigned bar_gen = 0;

// Dynamic smem: 74KB/CTA. Row stride 144B = 64 bf16 + 16B pad (ldmatrix-legal,
// 36-word stride -> conflict-free bank walk).
#define TROW 144
// Phase A (128-row tiles):            Phase C:
#define A_KH 0
#define A_KL 18432
#define A_QH 36864
#define A_QL 55296
#define C_MH 0            // 64-row MT hi
#define C_ML 9216         // 64-row MT lo
#define C_VH 36864        // 128-row V hi
#define C_VL 55296        // 128-row V lo
#define SMEM_BYTES 73728

__device__ __forceinline__ uint32_t smem_u32(const void* p){
    uint32_t a;
    asm("{ .reg .u64 t; cvta.to.shared.u64 t, %1; cvt.u32.u64 %0, t; }" : "=r"(a) : "l"(p));
    return a;
}
__device__ __forceinline__ uint32_t bf16x2_of(float fo, float fe){
    uint32_t r;
    asm("cvt.rn.bf16x2.f32 %0, %1, %2;" : "=r"(r) : "f"(fo), "f"(fe));
    return r;
}
// split fp32 (fe=even idx, fo=odd idx) -> hi word {bf16(fo),bf16(fe)} + residual
__device__ __forceinline__ void cvt_pair(float fe, float fo, uint32_t &hi, uint32_t &lo){
    hi = bf16x2_of(fo, fe);
    float he = __uint_as_float(hi << 16);
    float ho = __uint_as_float(hi & 0xffff0000u);
    lo = bf16x2_of(fo - ho, fe - he);
}
__device__ __forceinline__ void mma16816(float* c, const uint32_t* a,
                                         uint32_t b0, uint32_t b1){
    asm("mma.sync.aligned.m16n8k16.row.col.f32.bf16.bf16.f32 "
        "{%0,%1,%2,%3}, {%4,%5,%6,%7}, {%8,%9}, {%0,%1,%2,%3};"
        : "+f"(c[0]), "+f"(c[1]), "+f"(c[2]), "+f"(c[3])
        : "r"(a[0]), "r"(a[1]), "r"(a[2]), "r"(a[3]), "r"(b0), "r"(b1));
}
__device__ __forceinline__ void ldsm4(uint32_t* r, uint32_t addr){
    asm volatile("ldmatrix.sync.aligned.m8n8.x4.shared.b16 {%0,%1,%2,%3}, [%4];"
        : "=r"(r[0]), "=r"(r[1]), "=r"(r[2]), "=r"(r[3]) : "r"(addr));
}
__device__ __forceinline__ void ldsm4t(uint32_t* r, uint32_t addr){
    asm volatile("ldmatrix.sync.aligned.m8n8.x4.trans.shared.b16 {%0,%1,%2,%3}, [%4];"
        : "=r"(r[0]), "=r"(r[1]), "=r"(r[2]), "=r"(r[3]) : "r"(addr));
}
__device__ __forceinline__ void grid_barrier(){
    __threadfence();
    __syncthreads();
    if (threadIdx.x == 0) {
        unsigned gen = bar_gen;
        unsigned arrived = atomicAdd(&bar_cnt, 1);
        if (arrived == gridDim.x - 1) {
            bar_cnt = 0;
            __threadfence();
            bar_gen = gen + 1;
        } else {
            while (bar_gen == gen) { }     // plain spin (nanosleep regressed)
        }
    }
    __syncthreads();
    __threadfence();
}

// Stage 16 fp32 (one row-chunk) as bf16 hi+lo into natural-layout tiles.
__device__ __forceinline__ void stage_tile(unsigned char* hiB, unsigned char* loB,
                                           const float4* f, int row, int chunk){
    uint32_t h[8], L[8];
#pragma unroll
    for (int j = 0; j < 4; j++){
        cvt_pair(f[j].x, f[j].y, h[2*j],   L[2*j]);
        cvt_pair(f[j].z, f[j].w, h[2*j+1], L[2*j+1]);
    }
    uint4* dh = (uint4*)(hiB + row * TROW + chunk * 32);
    dh[0] = make_uint4(h[0], h[1], h[2], h[3]);
    dh[1] = make_uint4(h[4], h[5], h[6], h[7]);
    uint4* dl = (uint4*)(loB + row * TROW + chunk * 32);
    dl[0] = make_uint4(L[0], L[1], L[2], L[3]);
    dl[1] = make_uint4(L[4], L[5], L[6], L[7]);
}

// ---------------------------------------------------------------------------
// 256 blocks x 256 threads, 2 CTAs/SM, 74KB dynamic smem, ONE grid barrier.
// Phase A: LDG all 128 K/Q rows -> stage -> sync -> 8 contiguous ks MMA
//          sections -> [LDG V] -> atomic epilogue -> sync -> stage V (both).
// barrier -> Phase C: LDG+stage MT -> sync -> 4 ks x 4 n-tiles MMA over the
//          full 128-row V tile (warp m-tiles of 16) -> write O.
// ---------------------------------------------------------------------------
__global__ __launch_bounds__(NT, 2)
void fused_attn_hmma7(const float* __restrict__ Q, const float* __restrict__ K,
                      const float* __restrict__ V, float* __restrict__ O)
{
    extern __shared__ __align__(16) unsigned char sm[];
    const uint32_t sb = smem_u32(sm);

    const int t = threadIdx.x, warp = t >> 5, lane = t & 31;
    const int g = lane >> 2, tg = lane & 3;         // mma C/epilogue ids
    const int grp = lane >> 3, li = lane & 7;       // ldmatrix ids
    const int half8 = (grp & 1) << 3;
    const int krow  = ((grp >> 1) << 3) + li;       // trans-ldmatrix stored row
    const int wm = warp & 3, wn = warp >> 2;        // phase-A warp tile
    const int m0 = wm * 16, n0 = wn * 32;
    const int blk = blockIdx.x, b = blk >> 4, c = blk & 15;

    const int p = (int)(bar_gen & 1u);              // buffer parity

    const float* Kc = K + ((size_t)b * SEQ + (size_t)c * 128) * DIM;
    const float* Qc = Q + ((size_t)b * SEQ + (size_t)c * 128) * DIM;
    const float* Vc = V + ((size_t)b * SEQ + (size_t)c * 128) * DIM;

    // ========================== Phase A ====================================
    {
        // LDG all 128 rows of K and Q (2 row-chunk items per thread per tensor)
        float4 fK[2][4], fQ[2][4];
#pragma unroll
        for (int r = 0; r < 2; r++) {
            int item = t + 256 * r, row = item >> 2, ch = item & 3;
            const float4* pk = (const float4*)(Kc + (size_t)row * DIM + ch * 16);
            const float4* pq = (const float4*)(Qc + (size_t)row * DIM + ch * 16);
#pragma unroll
            for (int j = 0; j < 4; j++){ fK[r][j] = pk[j]; fQ[r][j] = pq[j]; }
        }
#pragma unroll
        for (int r = 0; r < 2; r++) {
            int item = t + 256 * r, row = item >> 2, ch = item & 3;
            stage_tile(sm + A_KH, sm + A_KL, fK[r], row, ch);
            stage_tile(sm + A_QH, sm + A_QL, fQ[r], row, ch);
        }
        __syncthreads();

        float acc[4][4];
#pragma unroll
        for (int q = 0; q < 4; q++)
#pragma unroll
            for (int i = 0; i < 4; i++) acc[q][i] = 0.0f;

        const uint32_t aB  = sb + A_KH + krow * TROW + 2 * (m0 + half8);
        const uint32_t bB0 = sb + A_QH + krow * TROW + 2 * (n0 + half8);
        const uint32_t bB1 = bB0 + 32;

#pragma unroll
        for (int ks = 0; ks < 8; ks++) {
            uint32_t ah[4], al[4], bh[4], bl[4];
            ldsm4t(ah, aB + ks * 2304);
            ldsm4t(al, aB + ks * 2304 + 18432);
            ldsm4t(bh, bB0 + ks * 2304);
            ldsm4t(bl, bB0 + ks * 2304 + 18432);
            mma16816(acc[0], ah, bh[0], bh[2]);
            mma16816(acc[0], ah, bl[0], bl[2]);
            mma16816(acc[0], al, bh[0], bh[2]);
            mma16816(acc[1], ah, bh[1], bh[3]);
            mma16816(acc[1], ah, bl[1], bl[3]);
            mma16816(acc[1], al, bh[1], bh[3]);
            ldsm4t(bh, bB1 + ks * 2304);
            ldsm4t(bl, bB1 + ks * 2304 + 18432);
            mma16816(acc[2], ah, bh[0], bh[2]);
            mma16816(acc[2], ah, bl[0], bl[2]);
            mma16816(acc[2], al, bh[0], bh[2]);
            mma16816(acc[3], ah, bh[1], bh[3]);
            mma16816(acc[3], ah, bl[1], bl[3]);
            mma16816(acc[3], al, bh[1], bh[3]);
        }

        // LDG V (all 128 rows) — flies during the atomic epilogue
        float4 fV[2][4];
#pragma unroll
        for (int r = 0; r < 2; r++) {
            int item = t + 256 * r, row = item >> 2, ch = item & 3;
            const float4* pv = (const float4*)(Vc + (size_t)row * DIM + ch * 16);
#pragma unroll
            for (int j = 0; j < 4; j++) fV[r][j] = pv[j];
        }

        // Epilogue: C[m=d1][n=d2] -> atomicAdd into M_final[p] at P[d2][d1].
        float* Mf = M_final[p] + (size_t)b * 4096;
#pragma unroll
        for (int q = 0; q < 4; q++) {
            int d2 = n0 + q * 8 + tg * 2;
            int d1 = m0 + g;
            atomicAdd(&Mf[d2 * 64 + d1],           acc[q][0]);
            atomicAdd(&Mf[(d2 + 1) * 64 + d1],     acc[q][1]);
            atomicAdd(&Mf[d2 * 64 + d1 + 8],       acc[q][2]);
            atomicAdd(&Mf[(d2 + 1) * 64 + d1 + 8], acc[q][3]);
        }

        // Zero the OTHER buffer for the next launch (stream-ordered).
        M_final[1 - p][blk * 256 + t] = 0.0f;

        __syncthreads();                 // all Q-tile readers done
#pragma unroll
        for (int r = 0; r < 2; r++) {    // stage V into (former Q) region
            int item = t + 256 * r, row = item >> 2, ch = item & 3;
            stage_tile(sm + C_VH, sm + C_VL, fV[r], row, ch);
        }
    }

    grid_barrier();     // all atomics into M_final[p] complete & visible

    // ========================== Phase C ====================================
    {
        // LDG + stage MT[d][dp] (P layout, L2-hot) into former K region.
        {
            const int d = t >> 2, wq = t & 3;
            const float4* bM = (const float4*)(M_final[p] + (size_t)b * 4096 + d * 64 + wq * 16);
            float4 fM[4];
#pragma unroll
            for (int j = 0; j < 4; j++) fM[j] = bM[j];
#pragma unroll
            for (int j = 0; j < 4; j++) {
                uint32_t hi, lo;
                int w = wq * 8 + 2 * j;
                cvt_pair(fM[j].x, fM[j].y, hi, lo);
                *(uint32_t*)(sm + C_MH + d * TROW + w * 4) = hi;
                *(uint32_t*)(sm + C_ML + d * TROW + w * 4) = lo;
                cvt_pair(fM[j].z, fM[j].w, hi, lo);
                *(uint32_t*)(sm + C_MH + d * TROW + (w + 1) * 4) = hi;
                *(uint32_t*)(sm + C_ML + d * TROW + (w + 1) * 4) = lo;
            }
        }
        __syncthreads();

        // Warp m-tiles of 16 across all 128 V rows; n spans all 64 MT rows.
        const int m0c = warp * 16;
        const uint32_t vB = sb + C_VH + (m0c + half8 + li) * TROW + ((grp >> 1) << 4);
        const uint32_t mB = sb + C_MH + (half8 + li) * TROW + ((grp >> 1) << 4);

        float acc2[8][4];
#pragma unroll
        for (int q = 0; q < 8; q++)
#pragma unroll
            for (int i = 0; i < 4; i++) acc2[q][i] = 0.0f;

#pragma unroll
        for (int ks = 0; ks < 4; ks++) {
            uint32_t ah[4], al[4];
            ldsm4(ah, vB + ks * 32);
            ldsm4(al, vB + ks * 32 + 18432);
#pragma unroll
            for (int nb = 0; nb < 4; nb++) {
                uint32_t bh[4], bl[4];
                ldsm4(bh, mB + nb * (16 * TROW) + ks * 32);
                ldsm4(bl, mB + nb * (16 * TROW) + ks * 32 + 9216);
                mma16816(acc2[2 * nb],     ah, bh[0], bh[2]);
                mma16816(acc2[2 * nb],     ah, bl[0], bl[2]);
                mma16816(acc2[2 * nb],     al, bh[0], bh[2]);
                mma16816(acc2[2 * nb + 1], ah, bh[1], bh[3]);
                mma16816(acc2[2 * nb + 1], ah, bl[1], bl[3]);
                mma16816(acc2[2 * nb + 1], al, bh[1], bh[3]);
            }
        }

        // Write O: rows c*128 + m0c + g (+8), cols j*8 + 2tg
        float* Ob = O + ((size_t)b * SEQ + (size_t)c * 128 + m0c) * DIM;
#pragma unroll
        for (int j = 0; j < 8; j++) {
            int col = j * 8 + tg * 2;
            *(float2*)(Ob + (size_t)g * DIM + col) =
                make_float2(acc2[j][0], acc2[j][1]);
            *(float2*)(Ob + (size_t)(g + 8) * DIM + col) =
                make_float2(acc2[j][2], acc2[j][3]);
        }
    }
}

// ---------------------------------------------------------------------------
extern "C" void kernel_launch(void* const* d_in, const int* in_sizes, int n_in,
                              void* d_out, int out_size) {
    const float* Q = (const float*)d_in[0];
    const float* K = (const float*)d_in[1];
    const float* V = (const float*)d_in[2];
    float* O = (float*)d_out;

    cudaFuncSetAttribute(fused_attn_hmma7,
                         cudaFuncAttributeMaxDynamicSharedMemorySize, SMEM_BYTES);
    fused_attn_hmma7<<<NBLK, NT, SMEM_BYTES>>>(Q, K, V, O);
}